// round 7
// baseline (speedup 1.0000x reference)
#include <cuda_runtime.h>
#include <cuda.h>
#include <cuda_fp16.h>
#include <math.h>
#include <stdint.h>

#define TT 512
#define NN 256
#define CC 256
#define SS 48
#define LL 97
#define LOG2E 1.4426950408889634f
#define LN2   0.6931471805599453f

// ---------------- phase B config ----------------
#define ROWS 2                      // batch rows per CTA (one per compute warp)
#define CHUNK 16                    // timesteps per ring buffer
#define NBUF 4
#define NCHUNK (TT / CHUNK)         // 32
#define GRID (NN / ROWS)            // 128
#define SLOTS 64                    // compact channels per (t,n): 48 labels + blank@48,49 + pad
#define TILE_HALVES (ROWS * SLOTS)  // per-timestep halves
#define BUF_HALVES (CHUNK * TILE_HALVES)
#define BUF_BYTES (BUF_HALVES * 2)          // 4096 B per chunk
#define SMEM_BYTES (NBUF * BUF_BYTES)       // 16 KB
#define NTHREADS 96                 // 2 compute warps + 1 producer warp

// ---------------- phase A config ----------------
#define A_ITER 4
#define A_BLOCKS ((TT * NN) / (8 * A_ITER))   // 4096

__device__ __half g_compact[(size_t)TT * NN * SLOTS];   // 16 MB scratch
__device__ float g_loss_n[NN];
__device__ int   g_count;           // zero-init; self-resetting per launch

__device__ __forceinline__ uint32_t s2u(const void* p) {
    return (uint32_t)__cvta_generic_to_shared(p);
}
__device__ __forceinline__ float ex2f(float x) {
    float y; asm("ex2.approx.ftz.f32 %0, %1;" : "=f"(y) : "f"(x)); return y;
}
__device__ __forceinline__ float lg2f(float x) {
    float y; asm("lg2.approx.ftz.f32 %0, %1;" : "=f"(y) : "f"(x)); return y;
}

__device__ __forceinline__ void mbar_wait(uint32_t addr, uint32_t parity) {
    asm volatile(
        "{\n"
        ".reg .pred P;\n"
        "WL%=:\n"
        "mbarrier.try_wait.parity.acquire.cta.shared::cta.b64 P, [%0], %1, 0x989680;\n"
        "@P bra WD%=;\n"
        "bra WL%=;\n"
        "WD%=:\n"
        "}\n" :: "r"(addr), "r"(parity) : "memory");
}

// ================= Phase A: gather 256 -> 64 compact fp16 log2-probs =================
// layout per (t,n): slot 2s   = labels[n,2s]   (s = lane, s<24)
//                   slot 2s+1 = labels[n,2s+1]
//                   slot 48,49 = blank (channel 0)
//                   slot 50..63 = 0 (pad, never read)
__global__ __launch_bounds__(256)
void gather_kernel(const float* __restrict__ logits,
                   const int*   __restrict__ labels)
{
    __shared__ float srow[8][CC];
    const int lane = threadIdx.x & 31;
    const int wl   = threadIdx.x >> 5;
    const int w    = blockIdx.x * 8 + wl;       // global warp id [0, 32768)
    const int n    = w & (NN - 1);
    const int tg   = w >> 8;                    // [0, 128)

    int ch0 = 0, ch1 = 0;
    if (lane < 24) {
        int2 lp = *(const int2*)(labels + n * SS + 2 * lane);
        ch0 = lp.x; ch1 = lp.y;
    }

    #pragma unroll
    for (int i = 0; i < A_ITER; i++) {
        const int t = tg * A_ITER + i;
        const float4* src = (const float4*)(logits + ((size_t)t * NN + n) * CC);
        float4 v0 = src[lane];
        float4 v1 = src[lane + 32];
        ((float4*)srow[wl])[lane]      = v0;
        ((float4*)srow[wl])[lane + 32] = v1;
        __syncwarp();
        float g0 = srow[wl][ch0] * LOG2E;
        float g1 = srow[wl][ch1] * LOG2E;
        __half2 h = __floats2half2_rn(g0, g1);
        if (lane >= 25) h = __floats2half2_rn(0.0f, 0.0f);   // pad slots 50..63
        *(__half2*)(g_compact + ((size_t)t * NN + n) * SLOTS + 2 * lane) = h;
        __syncwarp();
    }
}

// ================= Phase B: serial alpha recursion on compact tiles =================
__global__ __launch_bounds__(NTHREADS, 1)
void ctc_kernel(const __grid_constant__ CUtensorMap tmap,
                const int*   __restrict__ labels,
                const int*   __restrict__ pred_sizes,
                const int*   __restrict__ tgt_sizes,
                float*       __restrict__ out)
{
    extern __shared__ __align__(128) __half tiles[];
    __shared__ __align__(8) unsigned long long mb_full[NBUF];
    __shared__ __align__(8) unsigned long long mb_empty[NBUF];
    __shared__ float red[3];
    __shared__ int s_last;

    const int tid  = threadIdx.x;
    const int wid  = tid >> 5;
    const int lane = tid & 31;

    if (tid == 0) {
        #pragma unroll
        for (int b = 0; b < NBUF; b++) {
            asm volatile("mbarrier.init.shared.b64 [%0], %1;" :: "r"(s2u(&mb_full[b])),  "r"(1));
            asm volatile("mbarrier.init.shared.b64 [%0], %1;" :: "r"(s2u(&mb_empty[b])), "r"(ROWS));
        }
        asm volatile("fence.proxy.async.shared::cta;" ::: "memory");
    }
    __syncthreads();

    if (wid == ROWS) {
        // ---------------- producer: ONE 3D tensor load (4 KB) per chunk ----------------
        if (lane == 0) {
            const CUtensorMap* tm = &tmap;
            asm volatile("prefetch.tensormap [%0];" :: "l"(tm));
            const int n0 = blockIdx.x * ROWS;
            #pragma unroll 1
            for (int c = 0; c < NCHUNK; c++) {
                const int b = c % NBUF;
                const int r = c / NBUF;
                if (c >= NBUF) mbar_wait(s2u(&mb_empty[b]), (r - 1) & 1);
                uint32_t f = s2u(&mb_full[b]);
                asm volatile("mbarrier.arrive.expect_tx.shared.b64 _, [%0], %1;"
                             :: "r"(f), "r"(BUF_BYTES) : "memory");
                uint32_t dst = s2u(&tiles[b * BUF_HALVES]);
                asm volatile("cp.async.bulk.tensor.3d.shared::cta.global.tile.mbarrier::complete_tx::bytes "
                             "[%0], [%1, {%2, %3, %4}], [%5];"
                             :: "r"(dst), "l"(tm),
                                "r"(0), "r"(n0), "r"(c * CHUNK),
                                "r"(f) : "memory");
            }
        }
    } else {
        // ---------------- compute warps (one batch row each) ----------------
        const int n = blockIdx.x * ROWS + wid;
        const int k = lane;
        int lab_a = (2 * k     < SS) ? labels[n * SS + 2 * k]     : 0;  // state 4k+1
        int lab_b = (2 * k + 1 < SS) ? labels[n * SS + 2 * k + 1] : 0;  // state 4k+3
        int lab_p = (2 * k - 1 >= 0) ? labels[n * SS + 2 * k - 1] : 0;
        const float sk1f = ((lab_a != 0) && (lab_a != lab_p)) ? 1.0f : 0.0f;
        const float sk3f = ((lab_b != 0) && (lab_b != lab_a)) ? 1.0f : 0.0f;
        const int in_len = pred_sizes[n];
        const int pair_off = (lane < 24) ? 2 * lane : 48;   // half2 slot offset for (lab_a, lab_b)

        float a0 = 0.0f, a1 = 0.0f, a2 = 0.0f, a3 = 0.0f;
        int   X  = 0;                               // stored = true * 2^(-X)
        float xs = (lane == 0) ? 0.0f : 1.0f;       // 2^(X_prev - X), lane0 -> 0

        #pragma unroll 1
        for (int c = 0; c < NCHUNK; c++) {
            const int b = c % NBUF;
            mbar_wait(s2u(&mb_full[b]), (c / NBUF) & 1);

            #pragma unroll
            for (int j = 0; j < CHUNK; j++) {
                const int t = c * CHUNK + j;
                const __half* rp = tiles + ((b * CHUNK + j) * ROWS + wid) * SLOTS;
                if (t < in_len) {
                    __half2 hp = *(const __half2*)(rp + pair_off);   // (lab_a, lab_b) log2-probs
                    float lb0 = __half2float(rp[48]);                // blank log2-prob
                    float la  = __half2float(__low2half(hp));
                    float lb  = __half2float(__high2half(hp));
                    if (t == 0) {
                        if (lane == 0) {
                            a0 = ex2f(lb0);
                            a1 = ex2f(la);
                        }
                    } else {
                        float p0 = ex2f(lb0);
                        float pa = ex2f(la);
                        float pc = ex2f(lb);
                        float p3 = __shfl_up_sync(0xffffffffu, a3, 1);
                        float q3 = p3 * xs;                   // neighbor a3, rescaled (0 on lane 0)
                        float t01 = a0 + a1;
                        float t23 = a2 + a3;
                        float n0v = (a0 + q3) * p0;
                        float n1v = fmaf(sk1f, q3, t01) * pa;
                        float n2v = (a1 + a2) * p0;
                        float n3v = fmaf(sk3f, a1, t23) * pc;
                        a0 = n0v; a1 = n1v; a2 = n2v; a3 = n3v;
                    }
                    if ((t & 3) == 3) {
                        // per-lane power-of-2 renormalization
                        float mx = fmaxf(fmaxf(a0, a1), fmaxf(a2, a3));
                        int Xp = __shfl_up_sync(0xffffffffu, X, 1);   // neighbor X (pre-update)
                        unsigned u = __float_as_uint(mx);
                        int e = (int)(u >> 23);
                        if (e > 0) {
                            float scale = __uint_as_float((unsigned)(254 - e) << 23);
                            X += e - 127;
                            a0 *= scale; a1 *= scale; a2 *= scale; a3 *= scale;
                        } else if (mx == 0.0f && lane > 0) {
                            X = Xp;                 // adopt neighbor frame while empty
                        }
                        // rebuild cross-lane rescale factor for the next window
                        int Xp2 = __shfl_up_sync(0xffffffffu, X, 1);
                        int d = Xp2 - X;
                        d = max(-126, min(126, d));
                        xs = __uint_as_float((unsigned)(d + 127) << 23);
                        if (lane == 0) xs = 0.0f;
                    }
                }
            }

            if (lane == 0)
                asm volatile("mbarrier.arrive.shared.b64 _, [%0];"
                             :: "r"(s2u(&mb_empty[b])) : "memory");
        }

        // per-row loss: true log2(alpha_l) = lg2(stored) + X_lane
        {
            int tl = tgt_sizes[n];
            int i1 = 2 * tl - 1, i2 = 2 * tl;
            int sel1 = i1 & 3, sl1 = i1 >> 2;
            float x1 = (sel1 == 0) ? a0 : (sel1 == 1) ? a1 : (sel1 == 2) ? a2 : a3;
            x1 = __shfl_sync(0xffffffffu, x1, sl1);
            float X1 = (float)__shfl_sync(0xffffffffu, X, sl1);
            int sel2 = i2 & 3, sl2 = i2 >> 2;
            float x2 = (sel2 == 0) ? a0 : (sel2 == 1) ? a1 : (sel2 == 2) ? a2 : a3;
            x2 = __shfl_sync(0xffffffffu, x2, sl2);
            float X2 = (float)__shfl_sync(0xffffffffu, X, sl2);
            float l1 = lg2f(x1) + X1;    // x==0 -> -inf
            float l2 = lg2f(x2) + X2;
            float m  = fmaxf(l1, l2);
            float dd = fminf(l1, l2) - m;
            float lt = m + lg2f(1.0f + ex2f(dd));   // both -inf -> NaN -> sanitized
            float loss = -LN2 * lt;
            if (!(loss <= 1e29f)) loss = 0.0f;      // inf/NaN -> 0 (zero_infinity)
            if (lane == 0) g_loss_n[n] = loss / (float)tl;
        }
    }

    // fused mean-reduction: last CTA to finish does it
    __syncthreads();
    if (tid == 0) {
        __threadfence();
        int old = atomicAdd(&g_count, 1);
        s_last = (old == (int)gridDim.x - 1) ? 1 : 0;
    }
    __syncthreads();
    if (s_last) {
        __threadfence();
        float v = 0.0f;
        for (int i = tid; i < NN; i += NTHREADS) v += __ldcg(&g_loss_n[i]);
        #pragma unroll
        for (int o = 16; o; o >>= 1) v += __shfl_down_sync(0xffffffffu, v, o);
        if (lane == 0) red[wid] = v;
        __syncthreads();
        if (tid == 0) {
            float m = (red[0] + red[1] + red[2]) / (float)NN;
            if (isnan(m) || isinf(m)) m = 0.0f;
            out[0] = m;
            g_count = 0;   // reset for next graph replay
        }
    }
}

typedef CUresult (*EncodeTiledFn)(
    CUtensorMap*, CUtensorMapDataType, cuuint32_t, void*,
    const cuuint64_t*, const cuuint64_t*, const cuuint32_t*, const cuuint32_t*,
    CUtensorMapInterleave, CUtensorMapSwizzle, CUtensorMapL2promotion,
    CUtensorMapFloatOOBfill);

extern "C" void kernel_launch(void* const* d_in, const int* in_sizes, int n_in,
                              void* d_out, int out_size)
{
    const float* logits     = (const float*)d_in[0];
    const int*   labels     = (const int*)  d_in[1];
    const int*   pred_sizes = (const int*)  d_in[2];
    const int*   tgt_sizes  = (const int*)  d_in[3];
    float*       out        = (float*)d_out;

    // Tensor map over the compact fp16 buffer: dims [SLOTS, N, T], box [SLOTS, ROWS, CHUNK]
    CUtensorMap tmap;
    {
        void* compact_ptr = nullptr;
        cudaGetSymbolAddress(&compact_ptr, g_compact);
        void* fn = nullptr;
        cudaDriverEntryPointQueryResult qr;
        cudaGetDriverEntryPoint("cuTensorMapEncodeTiled", &fn,
                                cudaEnableDefault, &qr);
        EncodeTiledFn encode = (EncodeTiledFn)fn;
        cuuint64_t dims[3]    = {SLOTS, NN, TT};
        cuuint64_t strides[2] = {(cuuint64_t)SLOTS * 2, (cuuint64_t)NN * SLOTS * 2};
        cuuint32_t box[3]     = {SLOTS, ROWS, CHUNK};
        cuuint32_t estr[3]    = {1, 1, 1};
        encode(&tmap, CU_TENSOR_MAP_DATA_TYPE_UINT16, 3, compact_ptr,
               dims, strides, box, estr,
               CU_TENSOR_MAP_INTERLEAVE_NONE, CU_TENSOR_MAP_SWIZZLE_NONE,
               CU_TENSOR_MAP_L2_PROMOTION_L2_128B,
               CU_TENSOR_MAP_FLOAT_OOB_FILL_NONE);
    }

    gather_kernel<<<A_BLOCKS, 256>>>(logits, labels);
    cudaFuncSetAttribute(ctc_kernel, cudaFuncAttributeMaxDynamicSharedMemorySize, SMEM_BYTES);
    ctc_kernel<<<GRID, NTHREADS, SMEM_BYTES>>>(tmap, labels, pred_sizes, tgt_sizes, out);
}

// round 8
// speedup vs baseline: 1.1284x; 1.1284x over previous
#include <cuda_runtime.h>
#include <cuda.h>
#include <cuda_fp16.h>
#include <math.h>
#include <stdint.h>

#define TT 512
#define NN 256
#define CC 256
#define SS 48
#define LL 97
#define LOG2E 1.4426950408889634f
#define LN2   0.6931471805599453f

// ---------------- phase B config ----------------
#define ROWS 2                      // batch rows per CTA (one per compute warp)
#define CHUNK 16                    // timesteps per ring buffer
#define NBUF 4
#define NCHUNK (TT / CHUNK)         // 32
#define GRID (NN / ROWS)            // 128
#define SLOTS 64                    // compact channels per (t,n)
#define TILE_HALVES (ROWS * SLOTS)
#define BUF_HALVES (CHUNK * TILE_HALVES)
#define BUF_BYTES (BUF_HALVES * 2)          // 4096 B per chunk
#define SMEM_BYTES (NBUF * BUF_BYTES)       // 16 KB
#define NTHREADS 96                 // 2 compute warps + 1 producer warp

// ---------------- phase A config ----------------
#define A_ITER 4
#define A_BLOCKS ((TT * NN) / (8 * A_ITER))   // 4096

__device__ __half g_compact[(size_t)TT * NN * SLOTS];   // 16 MB scratch (linear fp16 probs)
__device__ float g_loss_n[NN];
__device__ int   g_count;           // zero-init; self-resetting per launch

__device__ __forceinline__ uint32_t s2u(const void* p) {
    return (uint32_t)__cvta_generic_to_shared(p);
}
__device__ __forceinline__ float lg2f(float x) {
    float y; asm("lg2.approx.ftz.f32 %0, %1;" : "=f"(y) : "f"(x)); return y;
}
__device__ __forceinline__ float ex2f(float x) {
    float y; asm("ex2.approx.ftz.f32 %0, %1;" : "=f"(y) : "f"(x)); return y;
}

__device__ __forceinline__ void mbar_wait(uint32_t addr, uint32_t parity) {
    asm volatile(
        "{\n"
        ".reg .pred P;\n"
        "WL%=:\n"
        "mbarrier.try_wait.parity.acquire.cta.shared::cta.b64 P, [%0], %1, 0x989680;\n"
        "@P bra WD%=;\n"
        "bra WL%=;\n"
        "WD%=:\n"
        "}\n" :: "r"(addr), "r"(parity) : "memory");
}

// ================= Phase A: gather 256 -> 64 compact fp16 LINEAR probs =================
// layout per (t,n): slot 2s = p(labels[n,2s]), slot 2s+1 = p(labels[n,2s+1]) (s<24)
//                   slot 48,49 = p(blank); 50..63 pad
__global__ __launch_bounds__(256)
void gather_kernel(const float* __restrict__ logits,
                   const int*   __restrict__ labels)
{
    __shared__ float srow[8][CC];
    const int lane = threadIdx.x & 31;
    const int wl   = threadIdx.x >> 5;
    const int w    = blockIdx.x * 8 + wl;
    const int n    = w & (NN - 1);
    const int tg   = w >> 8;

    int ch0 = 0, ch1 = 0;
    if (lane < 24) {
        int2 lp = *(const int2*)(labels + n * SS + 2 * lane);
        ch0 = lp.x; ch1 = lp.y;
    }

    #pragma unroll
    for (int i = 0; i < A_ITER; i++) {
        const int t = tg * A_ITER + i;
        const float4* src = (const float4*)(logits + ((size_t)t * NN + n) * CC);
        float4 v0 = src[lane];
        float4 v1 = src[lane + 32];
        ((float4*)srow[wl])[lane]      = v0;
        ((float4*)srow[wl])[lane + 32] = v1;
        __syncwarp();
        float p0 = ex2f(srow[wl][ch0] * LOG2E);   // linear prob
        float p1 = ex2f(srow[wl][ch1] * LOG2E);
        __half2 h = __floats2half2_rn(p0, p1);
        if (lane >= 25) h = __floats2half2_rn(0.0f, 0.0f);
        *(__half2*)(g_compact + ((size_t)t * NN + n) * SLOTS + 2 * lane) = h;
        __syncwarp();
    }
}

// ================= Phase B: serial alpha recursion (linear domain, no MUFU) =================
struct AState { float a0, a1, a2, a3, xs; int X; };

__device__ __forceinline__ void alpha_step(AState& s, float pb, float pa, float pc,
                                           float sk1f, float sk3f, int lane)
{
    float p3 = __shfl_up_sync(0xffffffffu, s.a3, 1);
    float q3 = p3 * s.xs;                  // neighbor a3 rescaled (0 on lane 0)
    float t01 = s.a0 + s.a1;
    float t23 = s.a2 + s.a3;
    float n0v = (s.a0 + q3) * pb;
    float n1v = fmaf(sk1f, q3, t01) * pa;
    float n2v = (s.a1 + s.a2) * pb;
    float n3v = fmaf(sk3f, s.a1, t23) * pc;
    s.a0 = n0v; s.a1 = n1v; s.a2 = n2v; s.a3 = n3v;
}

__device__ __forceinline__ void renorm(AState& s, int lane)
{
    float mx = fmaxf(fmaxf(s.a0, s.a1), fmaxf(s.a2, s.a3));
    int Xp = __shfl_up_sync(0xffffffffu, s.X, 1);
    int e  = (int)(__float_as_uint(mx) >> 23);
    int eu = (e > 0) ? e : 127;
    int Xn = s.X + (eu - 127);
    Xn = (mx == 0.0f && lane > 0) ? Xp : Xn;
    float scale = __uint_as_float((unsigned)(254 - eu) << 23);
    s.a0 *= scale; s.a1 *= scale; s.a2 *= scale; s.a3 *= scale;
    s.X = Xn;
    int Xp2 = __shfl_up_sync(0xffffffffu, s.X, 1);
    int d = min(126, max(-126, Xp2 - s.X));
    float x = __uint_as_float((unsigned)(d + 127) << 23);
    s.xs = (lane == 0) ? 0.0f : x;
}

__global__ __launch_bounds__(NTHREADS, 1)
void ctc_kernel(const __grid_constant__ CUtensorMap tmap,
                const int*   __restrict__ labels,
                const int*   __restrict__ pred_sizes,
                const int*   __restrict__ tgt_sizes,
                float*       __restrict__ out)
{
    extern __shared__ __align__(128) __half tiles[];
    __shared__ __align__(8) unsigned long long mb_full[NBUF];
    __shared__ __align__(8) unsigned long long mb_empty[NBUF];
    __shared__ float red[3];
    __shared__ int s_last;

    const int tid  = threadIdx.x;
    const int wid  = tid >> 5;
    const int lane = tid & 31;

    if (tid == 0) {
        #pragma unroll
        for (int b = 0; b < NBUF; b++) {
            asm volatile("mbarrier.init.shared.b64 [%0], %1;" :: "r"(s2u(&mb_full[b])),  "r"(1));
            asm volatile("mbarrier.init.shared.b64 [%0], %1;" :: "r"(s2u(&mb_empty[b])), "r"(ROWS));
        }
        asm volatile("fence.proxy.async.shared::cta;" ::: "memory");
    }
    __syncthreads();

    if (wid == ROWS) {
        // ---------------- producer: ONE 3D tensor load (4 KB) per chunk ----------------
        if (lane == 0) {
            const CUtensorMap* tm = &tmap;
            asm volatile("prefetch.tensormap [%0];" :: "l"(tm));
            const int n0 = blockIdx.x * ROWS;
            #pragma unroll 1
            for (int c = 0; c < NCHUNK; c++) {
                const int b = c % NBUF;
                const int r = c / NBUF;
                if (c >= NBUF) mbar_wait(s2u(&mb_empty[b]), (r - 1) & 1);
                uint32_t f = s2u(&mb_full[b]);
                asm volatile("mbarrier.arrive.expect_tx.shared.b64 _, [%0], %1;"
                             :: "r"(f), "r"(BUF_BYTES) : "memory");
                uint32_t dst = s2u(&tiles[b * BUF_HALVES]);
                asm volatile("cp.async.bulk.tensor.3d.shared::cta.global.tile.mbarrier::complete_tx::bytes "
                             "[%0], [%1, {%2, %3, %4}], [%5];"
                             :: "r"(dst), "l"(tm),
                                "r"(0), "r"(n0), "r"(c * CHUNK),
                                "r"(f) : "memory");
            }
        }
    } else {
        // ---------------- compute warps (one batch row each) ----------------
        const int n = blockIdx.x * ROWS + wid;
        const int k = lane;
        int lab_a = (2 * k     < SS) ? labels[n * SS + 2 * k]     : 0;
        int lab_b = (2 * k + 1 < SS) ? labels[n * SS + 2 * k + 1] : 0;
        int lab_p = (2 * k - 1 >= 0) ? labels[n * SS + 2 * k - 1] : 0;
        const float sk1f = ((lab_a != 0) && (lab_a != lab_p)) ? 1.0f : 0.0f;
        const float sk3f = ((lab_b != 0) && (lab_b != lab_a)) ? 1.0f : 0.0f;
        const int in_len = pred_sizes[n];
        const int pair_off = (lane < 24) ? 2 * lane : 48;

        AState s;
        s.a0 = 0.0f; s.a1 = 0.0f; s.a2 = 0.0f; s.a3 = 0.0f;
        s.X = 0;
        s.xs = (lane == 0) ? 0.0f : 1.0f;

        #pragma unroll 1
        for (int c = 0; c < NCHUNK; c++) {
            const int b = c % NBUF;
            mbar_wait(s2u(&mb_full[b]), (c / NBUF) & 1);
            const __half* base = tiles + ((size_t)b * CHUNK * ROWS + wid) * SLOTS;

            #pragma unroll
            for (int h = 0; h < 2; h++) {
                // ---- batch-load 8 steps of probs (off the dependency chain) ----
                float pa[8], pc[8], pb[8];
                #pragma unroll
                for (int j = 0; j < 8; j++) {
                    const __half* rp = base + (h * 8 + j) * TILE_HALVES;
                    __half2 hp = *(const __half2*)(rp + pair_off);
                    float2 f2 = __half22float2(hp);
                    pa[j] = f2.x; pc[j] = f2.y;
                    pb[j] = __half2float(rp[48]);
                }
                // ---- serial chain ----
                if (c == 0 && h == 0) {
                    if (lane == 0) { s.a0 = pb[0]; s.a1 = pa[0]; }   // t = 0 init
                    #pragma unroll
                    for (int j = 1; j < 8; j++) {
                        if (j < in_len) {
                            alpha_step(s, pb[j], pa[j], pc[j], sk1f, sk3f, lane);
                            if ((j & 3) == 3) renorm(s, lane);
                        }
                    }
                } else {
                    const int t0 = c * CHUNK + h * 8;
                    #pragma unroll
                    for (int j = 0; j < 8; j++) {
                        if (t0 + j < in_len) {
                            alpha_step(s, pb[j], pa[j], pc[j], sk1f, sk3f, lane);
                            if ((j & 3) == 3) renorm(s, lane);
                        }
                    }
                }
            }

            if (lane == 0)
                asm volatile("mbarrier.arrive.shared.b64 _, [%0];"
                             :: "r"(s2u(&mb_empty[b])) : "memory");
        }

        // per-row loss: true log2(alpha_l) = lg2(stored) + X_lane
        {
            int tl = tgt_sizes[n];
            int i1 = 2 * tl - 1, i2 = 2 * tl;
            int sel1 = i1 & 3, sl1 = i1 >> 2;
            float x1 = (sel1 == 0) ? s.a0 : (sel1 == 1) ? s.a1 : (sel1 == 2) ? s.a2 : s.a3;
            x1 = __shfl_sync(0xffffffffu, x1, sl1);
            float X1 = (float)__shfl_sync(0xffffffffu, s.X, sl1);
            int sel2 = i2 & 3, sl2 = i2 >> 2;
            float x2 = (sel2 == 0) ? s.a0 : (sel2 == 1) ? s.a1 : (sel2 == 2) ? s.a2 : s.a3;
            x2 = __shfl_sync(0xffffffffu, x2, sl2);
            float X2 = (float)__shfl_sync(0xffffffffu, s.X, sl2);
            float l1 = lg2f(x1) + X1;
            float l2 = lg2f(x2) + X2;
            float m  = fmaxf(l1, l2);
            float dd = fminf(l1, l2) - m;
            float lt = m + lg2f(1.0f + ex2f(dd));
            float loss = -LN2 * lt;
            if (!(loss <= 1e29f)) loss = 0.0f;      // inf/NaN -> 0 (zero_infinity)
            if (lane == 0) g_loss_n[n] = loss / (float)tl;
        }
    }

    // fused mean-reduction: last CTA to finish does it
    __syncthreads();
    if (tid == 0) {
        __threadfence();
        int old = atomicAdd(&g_count, 1);
        s_last = (old == (int)gridDim.x - 1) ? 1 : 0;
    }
    __syncthreads();
    if (s_last) {
        __threadfence();
        float v = 0.0f;
        for (int i = tid; i < NN; i += NTHREADS) v += __ldcg(&g_loss_n[i]);
        #pragma unroll
        for (int o = 16; o; o >>= 1) v += __shfl_down_sync(0xffffffffu, v, o);
        if (lane == 0) red[wid] = v;
        __syncthreads();
        if (tid == 0) {
            float m = (red[0] + red[1] + red[2]) / (float)NN;
            if (isnan(m) || isinf(m)) m = 0.0f;
            out[0] = m;
            g_count = 0;
        }
    }
}

typedef CUresult (*EncodeTiledFn)(
    CUtensorMap*, CUtensorMapDataType, cuuint32_t, void*,
    const cuuint64_t*, const cuuint64_t*, const cuuint32_t*, const cuuint32_t*,
    CUtensorMapInterleave, CUtensorMapSwizzle, CUtensorMapL2promotion,
    CUtensorMapFloatOOBfill);

extern "C" void kernel_launch(void* const* d_in, const int* in_sizes, int n_in,
                              void* d_out, int out_size)
{
    const float* logits     = (const float*)d_in[0];
    const int*   labels     = (const int*)  d_in[1];
    const int*   pred_sizes = (const int*)  d_in[2];
    const int*   tgt_sizes  = (const int*)  d_in[3];
    float*       out        = (float*)d_out;

    CUtensorMap tmap;
    {
        void* compact_ptr = nullptr;
        cudaGetSymbolAddress(&compact_ptr, g_compact);
        void* fn = nullptr;
        cudaDriverEntryPointQueryResult qr;
        cudaGetDriverEntryPoint("cuTensorMapEncodeTiled", &fn,
                                cudaEnableDefault, &qr);
        EncodeTiledFn encode = (EncodeTiledFn)fn;
        cuuint64_t dims[3]    = {SLOTS, NN, TT};
        cuuint64_t strides[2] = {(cuuint64_t)SLOTS * 2, (cuuint64_t)NN * SLOTS * 2};
        cuuint32_t box[3]     = {SLOTS, ROWS, CHUNK};
        cuuint32_t estr[3]    = {1, 1, 1};
        encode(&tmap, CU_TENSOR_MAP_DATA_TYPE_UINT16, 3, compact_ptr,
               dims, strides, box, estr,
               CU_TENSOR_MAP_INTERLEAVE_NONE, CU_TENSOR_MAP_SWIZZLE_NONE,
               CU_TENSOR_MAP_L2_PROMOTION_L2_128B,
               CU_TENSOR_MAP_FLOAT_OOB_FILL_NONE);
    }

    gather_kernel<<<A_BLOCKS, 256>>>(logits, labels);
    cudaFuncSetAttribute(ctc_kernel, cudaFuncAttributeMaxDynamicSharedMemorySize, SMEM_BYTES);
    ctc_kernel<<<GRID, NTHREADS, SMEM_BYTES>>>(tmap, labels, pred_sizes, tgt_sizes, out);
}

// round 10
// speedup vs baseline: 1.8904x; 1.6753x over previous
#include <cuda_runtime.h>
#include <math.h>
#include <stdint.h>

#define TT 512
#define NN 256
#define CC 256
#define SS 48
#define LL 97
#define LOG2E 1.4426950408889634f
#define LN2   0.6931471805599453f

#define ROWS 2                      // batch rows per CTA
#define CHUNK 16                    // timesteps per ring buffer
#define NBUF 4
#define NCHUNK (TT / CHUNK)         // 32
#define GRID (NN / ROWS)            // 128
#define SLOTS 64                    // floats per (t,row) tile
#define GW 8                        // gather warps (wid 0..7)
#define CW 2                        // compute warps (wid 8..9) - hi-wid = arbiter priority
#define NWARPS (GW + CW)
#define NTHREADS (NWARPS * 32)      // 320
#define TILE_F (ROWS * SLOTS)       // 128 floats per timestep
#define BUF_F (CHUNK * TILE_F)      // 2048 floats per buffer
#define RING_F (NBUF * BUF_F)       // 8192 floats = 32 KB
#define SCRATCH_F (GW * 2 * 512)    // 8 warps x 2 t x 512 floats = 32 KB
#define SMEM_BYTES ((RING_F + SCRATCH_F) * 4)   // 65536

__device__ float g_loss_n[NN];
__device__ int   g_count;           // zero-init; self-resetting per launch

__device__ __forceinline__ uint32_t s2u(const void* p) {
    return (uint32_t)__cvta_generic_to_shared(p);
}
__device__ __forceinline__ float ex2f(float x) {
    float y; asm("ex2.approx.ftz.f32 %0, %1;" : "=f"(y) : "f"(x)); return y;
}
__device__ __forceinline__ float lg2f(float x) {
    float y; asm("lg2.approx.ftz.f32 %0, %1;" : "=f"(y) : "f"(x)); return y;
}
__device__ __forceinline__ void mbar_wait(uint32_t addr, uint32_t parity) {
    asm volatile(
        "{\n"
        ".reg .pred P;\n"
        "WL%=:\n"
        "mbarrier.try_wait.parity.acquire.cta.shared::cta.b64 P, [%0], %1, 0x989680;\n"
        "@P bra WD%=;\n"
        "bra WL%=;\n"
        "WD%=:\n"
        "}\n" :: "r"(addr), "r"(parity) : "memory");
}

struct AState { float a0, a1, a2, a3, xs; int X; };

__device__ __forceinline__ void alpha_step(AState& s, float pb, float pa, float pc,
                                           float sk1f, float sk3f)
{
    float p3 = __shfl_up_sync(0xffffffffu, s.a3, 1);
    float q3 = p3 * s.xs;                  // neighbor a3 rescaled (0 on lane 0)
    float t01 = s.a0 + s.a1;
    float t23 = s.a2 + s.a3;
    float n0v = (s.a0 + q3) * pb;
    float n1v = fmaf(sk1f, q3, t01) * pa;
    float n2v = (s.a1 + s.a2) * pb;
    float n3v = fmaf(sk3f, s.a1, t23) * pc;
    s.a0 = n0v; s.a1 = n1v; s.a2 = n2v; s.a3 = n3v;
}

// PROVEN two-shfl renorm (round 8): second shfl broadcasts the FINAL post-adoption
// X so downstream xs always matches the neighbor's actual frame.
__device__ __forceinline__ void renorm(AState& s, int lane)
{
    float mx = fmaxf(fmaxf(s.a0, s.a1), fmaxf(s.a2, s.a3));
    int Xp = __shfl_up_sync(0xffffffffu, s.X, 1);      // neighbor X (pre-update)
    int e  = (int)(__float_as_uint(mx) >> 23);
    int eu = (e > 0) ? e : 127;
    int Xn = s.X + (eu - 127);
    Xn = (mx == 0.0f && lane > 0) ? Xp : Xn;           // empty lanes adopt neighbor frame
    float scale = __uint_as_float((unsigned)(254 - eu) << 23);
    s.a0 *= scale; s.a1 *= scale; s.a2 *= scale; s.a3 *= scale;
    s.X = Xn;
    int Xp2 = __shfl_up_sync(0xffffffffu, s.X, 1);     // neighbor FINAL X
    int d = min(126, max(-126, Xp2 - s.X));
    float x = __uint_as_float((unsigned)(d + 127) << 23);
    s.xs = (lane == 0) ? 0.0f : x;
}

__global__ __launch_bounds__(NTHREADS, 1)
void ctc_fused(const float* __restrict__ logits,
               const int*   __restrict__ labels,
               const int*   __restrict__ pred_sizes,
               const int*   __restrict__ tgt_sizes,
               float*       __restrict__ out)
{
    extern __shared__ __align__(128) float smem[];
    float* ring    = smem;                 // RING_F floats
    float* scratch = smem + RING_F;        // SCRATCH_F floats
    __shared__ __align__(8) unsigned long long mb_full[NBUF];
    __shared__ __align__(8) unsigned long long mb_empty[NBUF];
    __shared__ float red[NWARPS];
    __shared__ int s_last;

    const int tid  = threadIdx.x;
    const int wid  = tid >> 5;
    const int lane = tid & 31;
    const int n0   = blockIdx.x * ROWS;

    if (tid == 0) {
        #pragma unroll
        for (int b = 0; b < NBUF; b++) {
            asm volatile("mbarrier.init.shared.b64 [%0], %1;" :: "r"(s2u(&mb_full[b])),  "r"(2 * GW));
            asm volatile("mbarrier.init.shared.b64 [%0], %1;" :: "r"(s2u(&mb_empty[b])), "r"(CW));
        }
    }
    __syncthreads();

    if (wid < GW) {
        // ================= gather warps =================
        float* myscr = scratch + wid * 1024;          // 2 t-slots x 512 floats
        int ch00 = 0, ch01 = 0, ch10 = 0, ch11 = 0;
        if (lane < 24) {
            int2 l0 = *(const int2*)(labels + n0 * SS + 2 * lane);
            int2 l1 = *(const int2*)(labels + (n0 + 1) * SS + 2 * lane);
            ch00 = l0.x; ch01 = l0.y; ch10 = l1.x; ch11 = l1.y;
        }
        #pragma unroll 1
        for (int c = 0; c < NCHUNK; c++) {
            const int b = c % NBUF;
            if (c >= NBUF) mbar_wait(s2u(&mb_empty[b]), ((c / NBUF) - 1) & 1);
            const int ta = c * CHUNK + wid;
            const int tb = ta + 8;
            const float4* sa = (const float4*)(logits + ((size_t)ta * NN + n0) * CC);
            const float4* sb = (const float4*)(logits + ((size_t)tb * NN + n0) * CC);
            float4 va0 = sa[lane], va1 = sa[lane + 32], va2 = sa[lane + 64], va3 = sa[lane + 96];
            float4 vb0 = sb[lane], vb1 = sb[lane + 32], vb2 = sb[lane + 64], vb3 = sb[lane + 96];
            float4* d0 = (float4*)myscr;
            d0[lane] = va0; d0[lane + 32] = va1; d0[lane + 64] = va2; d0[lane + 96] = va3;
            float4* d1 = (float4*)(myscr + 512);
            d1[lane] = vb0; d1[lane + 32] = vb1; d1[lane + 64] = vb2; d1[lane + 96] = vb3;
            __syncwarp();
            if (lane <= 24) {
                #pragma unroll
                for (int s = 0; s < 2; s++) {
                    const float* base = myscr + s * 512;
                    const int j = (s == 0) ? wid : (wid + 8);
                    float p00 = ex2f(base[ch00]       * LOG2E);
                    float p01 = ex2f(base[ch01]       * LOG2E);
                    float p10 = ex2f(base[256 + ch10] * LOG2E);
                    float p11 = ex2f(base[256 + ch11] * LOG2E);
                    float* tp = ring + (size_t)(b * CHUNK + j) * TILE_F;
                    *(float2*)(tp + 2 * lane)         = make_float2(p00, p01);
                    *(float2*)(tp + SLOTS + 2 * lane) = make_float2(p10, p11);
                }
            }
            __syncwarp();
            if (lane == 0) {
                asm volatile("mbarrier.arrive.shared.b64 _, [%0];" :: "r"(s2u(&mb_full[b])) : "memory");
                asm volatile("mbarrier.arrive.shared.b64 _, [%0];" :: "r"(s2u(&mb_full[b])) : "memory");
            }
        }
    } else {
        // ================= compute warps (one batch row each) =================
        const int row = wid - GW;
        const int n = n0 + row;
        int lab_a = (2 * lane     < SS) ? labels[n * SS + 2 * lane]     : 0;
        int lab_b = (2 * lane + 1 < SS) ? labels[n * SS + 2 * lane + 1] : 0;
        int lab_p = (2 * lane - 1 >= 0) ? labels[n * SS + 2 * lane - 1] : 0;
        const float sk1f = ((lab_a != 0) && (lab_a != lab_p)) ? 1.0f : 0.0f;
        const float sk3f = ((lab_b != 0) && (lab_b != lab_a)) ? 1.0f : 0.0f;
        const int in_len = pred_sizes[n];
        const int pair_off = (lane < 24) ? 2 * lane : 48;

        AState s;
        s.a0 = 0.0f; s.a1 = 0.0f; s.a2 = 0.0f; s.a3 = 0.0f;
        s.X = 0;
        s.xs = (lane == 0) ? 0.0f : 1.0f;

        #pragma unroll 1
        for (int c = 0; c < NCHUNK; c++) {
            const int b = c % NBUF;
            mbar_wait(s2u(&mb_full[b]), (c / NBUF) & 1);
            const float* base = ring + (size_t)(b * CHUNK) * TILE_F + row * SLOTS;
            const bool fast = (c > 0) && ((c + 1) * CHUNK <= in_len);

            if (fast) {
                #pragma unroll
                for (int h = 0; h < 2; h++) {
                    float pa[8], pc[8], pb[8];
                    #pragma unroll
                    for (int j = 0; j < 8; j++) {
                        const float* rp = base + (h * 8 + j) * TILE_F;
                        float2 f2 = *(const float2*)(rp + pair_off);
                        pa[j] = f2.x; pc[j] = f2.y;
                        pb[j] = rp[48];
                    }
                    #pragma unroll
                    for (int j = 0; j < 8; j++) {
                        alpha_step(s, pb[j], pa[j], pc[j], sk1f, sk3f);
                        if ((j & 3) == 3) renorm(s, lane);
                    }
                }
            } else {
                #pragma unroll 1
                for (int j = 0; j < CHUNK; j++) {
                    const int t = c * CHUNK + j;
                    const float* rp = base + j * TILE_F;
                    if (t < in_len) {
                        float2 f2 = *(const float2*)(rp + pair_off);
                        float pbv = rp[48];
                        if (t == 0) {
                            if (lane == 0) { s.a0 = pbv; s.a1 = f2.x; }
                        } else {
                            alpha_step(s, pbv, f2.x, f2.y, sk1f, sk3f);
                        }
                        if ((t & 3) == 3) renorm(s, lane);
                    }
                }
            }

            if (lane == 0)
                asm volatile("mbarrier.arrive.shared.b64 _, [%0];" :: "r"(s2u(&mb_empty[b])) : "memory");
        }

        // per-row loss: true log2(alpha_l) = lg2(stored) + X_lane
        {
            int tl = tgt_sizes[n];
            int i1 = 2 * tl - 1, i2 = 2 * tl;
            int sel1 = i1 & 3, sl1 = i1 >> 2;
            float x1 = (sel1 == 0) ? s.a0 : (sel1 == 1) ? s.a1 : (sel1 == 2) ? s.a2 : s.a3;
            x1 = __shfl_sync(0xffffffffu, x1, sl1);
            float X1 = (float)__shfl_sync(0xffffffffu, s.X, sl1);
            int sel2 = i2 & 3, sl2 = i2 >> 2;
            float x2 = (sel2 == 0) ? s.a0 : (sel2 == 1) ? s.a1 : (sel2 == 2) ? s.a2 : s.a3;
            x2 = __shfl_sync(0xffffffffu, x2, sl2);
            float X2 = (float)__shfl_sync(0xffffffffu, s.X, sl2);
            float l1 = lg2f(x1) + X1;
            float l2 = lg2f(x2) + X2;
            float m  = fmaxf(l1, l2);
            float dd = fminf(l1, l2) - m;
            float lt = m + lg2f(1.0f + ex2f(dd));
            float loss = -LN2 * lt;
            if (!(loss <= 1e29f)) loss = 0.0f;      // inf/NaN -> 0 (zero_infinity)
            if (lane == 0) g_loss_n[n] = loss / (float)tl;
        }
    }

    // fused mean-reduction: last CTA to finish does it
    __syncthreads();
    if (tid == 0) {
        __threadfence();
        int old = atomicAdd(&g_count, 1);
        s_last = (old == (int)gridDim.x - 1) ? 1 : 0;
    }
    __syncthreads();
    if (s_last) {
        __threadfence();
        float v = 0.0f;
        for (int i = tid; i < NN; i += NTHREADS) v += __ldcg(&g_loss_n[i]);
        #pragma unroll
        for (int o = 16; o; o >>= 1) v += __shfl_down_sync(0xffffffffu, v, o);
        if (lane == 0) red[wid] = v;
        __syncthreads();
        if (tid == 0) {
            float m = 0.0f;
            #pragma unroll
            for (int w = 0; w < NWARPS; w++) m += red[w];
            m /= (float)NN;
            if (isnan(m) || isinf(m)) m = 0.0f;
            out[0] = m;
            g_count = 0;   // reset for next graph replay
        }
    }
}

extern "C" void kernel_launch(void* const* d_in, const int* in_sizes, int n_in,
                              void* d_out, int out_size)
{
    const float* logits     = (const float*)d_in[0];
    const int*   labels     = (const int*)  d_in[1];
    const int*   pred_sizes = (const int*)  d_in[2];
    const int*   tgt_sizes  = (const int*)  d_in[3];
    float*       out        = (float*)d_out;

    cudaFuncSetAttribute(ctc_fused, cudaFuncAttributeMaxDynamicSharedMemorySize, SMEM_BYTES);
    ctc_fused<<<GRID, NTHREADS, SMEM_BYTES>>>(logits, labels, pred_sizes, tgt_sizes, out);
}